// round 1
// baseline (speedup 1.0000x reference)
#include <cuda_runtime.h>

// ============================================================================
// StablePolicy3phase: out[b] = s @ Wsum - sum_h clamp(W_h s, -bn_h, bn_h) + 0.001*s
// where s = state - clamp(state, 0.97, 1.03)   (deadband)
//       W_h symmetric 3x3 from lambda^2, bn_h = 0.15*clip(b,0)/sum(clip(b,0))
// Identity used: relu(t-c) - relu(-t-c) == t - clamp(t,-c,c)  for c >= 0.
// ============================================================================

#define HN 256
#define TAB_STRIDE 20   // floats per h in the table (80 B, 16B-aligned)

__device__ float g_table[HN * TAB_STRIDE];
__device__ float g_wsum[8];

typedef unsigned long long u64;

__device__ __forceinline__ u64 pack2(float lo, float hi) {
    u64 r; asm("mov.b64 %0, {%1, %2};" : "=l"(r) : "f"(lo), "f"(hi)); return r;
}
__device__ __forceinline__ void unpack2(u64 v, float& lo, float& hi) {
    asm("mov.b64 {%0, %1}, %2;" : "=f"(lo), "=f"(hi) : "l"(v));
}
__device__ __forceinline__ u64 ffma2(u64 a, u64 b, u64 c) {
    u64 r; asm("fma.rn.f32x2 %0, %1, %2, %3;" : "=l"(r) : "l"(a), "l"(b), "l"(c)); return r;
}
__device__ __forceinline__ u64 fmul2(u64 a, u64 b) {
    u64 r; asm("mul.rn.f32x2 %0, %1, %2;" : "=l"(r) : "l"(a), "l"(b)); return r;
}
__device__ __forceinline__ u64 fadd2(u64 a, u64 b) {
    u64 r; asm("add.rn.f32x2 %0, %1, %2;" : "=l"(r) : "l"(a), "l"(b)); return r;
}

// deadband: s = v - clamp(v, 0.97, 1.03)
__device__ __forceinline__ float deadband(float v) {
    return v - fminf(fmaxf(v, 0.97f), 1.03f);
}

// ----------------------------------------------------------------------------
// Prep kernel: one block of 256 threads (one per h).
// Builds the per-h table: duplicated W-entry pairs for f32x2 math, bn and -bn.
// Also reduces sum(clip(b,0)) and Wsum (6 entries) across h.
// ----------------------------------------------------------------------------
__global__ void prep_kernel(const float* __restrict__ b,
                            const float* __restrict__ lam) {
    __shared__ float red[HN * 8];
    int h = threadIdx.x;

    float l2[6];
#pragma unroll
    for (int k = 0; k < 6; k++) { float v = lam[h * 6 + k]; l2[k] = v * v; }
    // basis order: (0,0),(1,0),(1,1),(2,0),(2,1),(2,2)
    float d0 = l2[0] + l2[1] + l2[3];   // W00
    float d1 = l2[1] + l2[2] + l2[4];   // W11
    float d2 = l2[3] + l2[4] + l2[5];   // W22
    float a  = -l2[1];                  // W01
    float c  = -l2[3];                  // W02
    float e  = -l2[4];                  // W12

    float b0 = fmaxf(b[h * 3 + 0], 0.0f);
    float b1 = fmaxf(b[h * 3 + 1], 0.0f);
    float b2 = fmaxf(b[h * 3 + 2], 0.0f);

    red[h * 8 + 0] = b0 + b1 + b2;
    red[h * 8 + 1] = d0;
    red[h * 8 + 2] = a;
    red[h * 8 + 3] = c;
    red[h * 8 + 4] = d1;
    red[h * 8 + 5] = e;
    red[h * 8 + 6] = d2;
    red[h * 8 + 7] = 0.0f;
    __syncthreads();

    for (int s = 128; s > 0; s >>= 1) {
        if (h < s) {
#pragma unroll
            for (int k = 0; k < 8; k++) red[h * 8 + k] += red[(h + s) * 8 + k];
        }
        __syncthreads();
    }

    if (h == 0) {
        g_wsum[0] = red[1];  // Wsum00
        g_wsum[1] = red[2];  // Wsum01
        g_wsum[2] = red[3];  // Wsum02
        g_wsum[3] = red[4];  // Wsum11
        g_wsum[4] = red[5];  // Wsum12
        g_wsum[5] = red[6];  // Wsum22
    }

    float inv = 0.15f / red[0];
    float bn0 = b0 * inv, bn1 = b1 * inv, bn2 = b2 * inv;

    float* t = g_table + h * TAB_STRIDE;
    t[0]  = d0;  t[1]  = d0;
    t[2]  = a;   t[3]  = a;
    t[4]  = c;   t[5]  = c;
    t[6]  = d1;  t[7]  = d1;
    t[8]  = e;   t[9]  = e;
    t[10] = d2;  t[11] = d2;
    t[12] = bn0; t[13] = bn1; t[14] = bn2;
    t[15] = -bn0; t[16] = -bn1; t[17] = -bn2;
    t[18] = 0.0f; t[19] = 0.0f;
}

// ----------------------------------------------------------------------------
// Main kernel: each thread handles 2 adjacent rows, packed via f32x2 math.
// 65536 threads = 512 blocks x 128.
// ----------------------------------------------------------------------------
__global__ __launch_bounds__(128) void main_kernel(
    const float* __restrict__ state, float* __restrict__ out) {
    __shared__ float tab[HN * TAB_STRIDE];

    // cooperative table load (1280 float4)
    {
        const float4* g4 = (const float4*)g_table;
        float4* s4 = (float4*)tab;
        for (int i = threadIdx.x; i < HN * TAB_STRIDE / 4; i += 128) s4[i] = g4[i];
    }
    __syncthreads();

    int g = blockIdx.x * 128 + threadIdx.x;   // row-pair id: rows 2g, 2g+1

    const float2* st = (const float2*)state + (size_t)g * 3;
    float2 v01  = st[0];   // rowA v0, rowA v1
    float2 v2_0 = st[1];   // rowA v2, rowB v0
    float2 v12  = st[2];   // rowB v1, rowB v2

    float sa0 = deadband(v01.x),  sa1 = deadband(v01.y),  sa2 = deadband(v2_0.x);
    float sb0 = deadband(v2_0.y), sb1 = deadband(v12.x),  sb2 = deadband(v12.y);

    u64 S0 = pack2(sa0, sb0);
    u64 S1 = pack2(sa1, sb1);
    u64 S2 = pack2(sa2, sb2);

    u64 acc0 = 0ull, acc1 = 0ull, acc2 = 0ull;   // (0.0f, 0.0f)

#pragma unroll 8
    for (int h = 0; h < HN; h++) {
        const float4* tp = (const float4*)(tab + h * TAB_STRIDE);
        float4 q0 = tp[0];   // d0 d0 a a
        float4 q1 = tp[1];   // c c d1 d1
        float4 q2 = tp[2];   // e e d2 d2
        float4 q3 = tp[3];   // bn0 bn1 bn2 -bn0
        float4 q4 = tp[4];   // -bn1 -bn2 pad pad

        u64 D0 = pack2(q0.x, q0.y);
        u64 A  = pack2(q0.z, q0.w);
        u64 C  = pack2(q1.x, q1.y);
        u64 D1 = pack2(q1.z, q1.w);
        u64 E  = pack2(q2.x, q2.y);
        u64 D2 = pack2(q2.z, q2.w);

        // sw = W s (symmetric), two rows packed
        u64 sw0 = ffma2(C, S2, ffma2(A,  S1, fmul2(D0, S0)));
        u64 sw1 = ffma2(E, S2, ffma2(D1, S1, fmul2(A,  S0)));
        u64 sw2 = ffma2(D2, S2, ffma2(E,  S1, fmul2(C,  S0)));

        float w0a, w0b, w1a, w1b, w2a, w2b;
        unpack2(sw0, w0a, w0b);
        unpack2(sw1, w1a, w1b);
        unpack2(sw2, w2a, w2b);

        // clamp(sw, -bn, bn)   (scalar FMNMX -> alu pipe, balances fma pipe)
        float t0a = fminf(fmaxf(w0a, q3.w), q3.x);
        float t0b = fminf(fmaxf(w0b, q3.w), q3.x);
        float t1a = fminf(fmaxf(w1a, q4.x), q3.y);
        float t1b = fminf(fmaxf(w1b, q4.x), q3.y);
        float t2a = fminf(fmaxf(w2a, q4.y), q3.z);
        float t2b = fminf(fmaxf(w2b, q4.y), q3.z);

        acc0 = fadd2(acc0, pack2(t0a, t0b));
        acc1 = fadd2(acc1, pack2(t1a, t1b));
        acc2 = fadd2(acc2, pack2(t2a, t2b));
    }

    float a0, a0b, a1, a1b, a2, a2b;
    unpack2(acc0, a0, a0b);
    unpack2(acc1, a1, a1b);
    unpack2(acc2, a2, a2b);

    float ws00 = g_wsum[0], ws01 = g_wsum[1], ws02 = g_wsum[2];
    float ws11 = g_wsum[3], ws12 = g_wsum[4], ws22 = g_wsum[5];

    // linear part: s @ Wsum (symmetric)
    float la0 = ws00 * sa0 + ws01 * sa1 + ws02 * sa2;
    float la1 = ws01 * sa0 + ws11 * sa1 + ws12 * sa2;
    float la2 = ws02 * sa0 + ws12 * sa1 + ws22 * sa2;
    float lb0 = ws00 * sb0 + ws01 * sb1 + ws02 * sb2;
    float lb1 = ws01 * sb0 + ws11 * sb1 + ws12 * sb2;
    float lb2 = ws02 * sb0 + ws12 * sb1 + ws22 * sb2;

    float oA0 = la0 - a0  + 0.001f * sa0;
    float oA1 = la1 - a1  + 0.001f * sa1;
    float oA2 = la2 - a2  + 0.001f * sa2;
    float oB0 = lb0 - a0b + 0.001f * sb0;
    float oB1 = lb1 - a1b + 0.001f * sb1;
    float oB2 = lb2 - a2b + 0.001f * sb2;

    float2* op = (float2*)out + (size_t)g * 3;
    op[0] = make_float2(oA0, oA1);
    op[1] = make_float2(oA2, oB0);
    op[2] = make_float2(oB1, oB2);
}

extern "C" void kernel_launch(void* const* d_in, const int* in_sizes, int n_in,
                              void* d_out, int out_size) {
    const float* state = (const float*)d_in[0];   // [131072, 3]
    const float* b     = (const float*)d_in[1];   // [256, 3]
    const float* lam   = (const float*)d_in[2];   // [256, 6]
    float* out = (float*)d_out;                   // [131072, 3]

    prep_kernel<<<1, HN>>>(b, lam);
    int groups = 131072 / 2;                      // 2 rows per thread
    main_kernel<<<groups / 128, 128>>>(state, out);
}

// round 2
// speedup vs baseline: 1.1175x; 1.1175x over previous
#include <cuda_runtime.h>

// ============================================================================
// StablePolicy3phase: out[b] = s @ Wsum - sum_h clamp(W_h s, -bn_h, bn_h) + 0.001*s
// where s = state - clamp(state, 0.97, 1.03)   (deadband)
//       W_h symmetric 3x3 from lambda^2, bn_h = 0.15*clip(b,0)/sum(clip(b,0))
// Identity: relu(t-c) - relu(-t-c) == t - clamp(t,-c,c)  for c >= 0.
//
// R2: h-loop split across lane halves (lanes 0-15: h<128, lanes 16-31: h>=128)
//     -> 2x warps (4096), shfl-combine epilogue. Table stored as packed f32x2
//     pairs loaded via ld.shared.v2.b64 (no repacking), TAB_STRIDE 16.
// ============================================================================

#define HN 256
#define TAB_STRIDE 16   // floats per h (64 B): d0d0 aa | cc d1d1 | ee d2d2 | bn0 bn1 bn2 pad

__device__ float g_table[HN * TAB_STRIDE];
__device__ float g_wsum[8];

typedef unsigned long long u64;

__device__ __forceinline__ u64 pack2(float lo, float hi) {
    u64 r; asm("mov.b64 %0, {%1, %2};" : "=l"(r) : "f"(lo), "f"(hi)); return r;
}
__device__ __forceinline__ void unpack2(u64 v, float& lo, float& hi) {
    asm("mov.b64 {%0, %1}, %2;" : "=f"(lo), "=f"(hi) : "l"(v));
}
__device__ __forceinline__ u64 ffma2(u64 a, u64 b, u64 c) {
    u64 r; asm("fma.rn.f32x2 %0, %1, %2, %3;" : "=l"(r) : "l"(a), "l"(b), "l"(c)); return r;
}
__device__ __forceinline__ u64 fmul2(u64 a, u64 b) {
    u64 r; asm("mul.rn.f32x2 %0, %1, %2;" : "=l"(r) : "l"(a), "l"(b)); return r;
}
__device__ __forceinline__ u64 fadd2(u64 a, u64 b) {
    u64 r; asm("add.rn.f32x2 %0, %1, %2;" : "=l"(r) : "l"(a), "l"(b)); return r;
}

__device__ __forceinline__ float deadband(float v) {
    return v - fminf(fmaxf(v, 0.97f), 1.03f);
}

// ----------------------------------------------------------------------------
// Prep kernel: one block of 256 threads (one per h).
// ----------------------------------------------------------------------------
__global__ void prep_kernel(const float* __restrict__ b,
                            const float* __restrict__ lam) {
    __shared__ float red[HN * 8];
    int h = threadIdx.x;

    float l2[6];
#pragma unroll
    for (int k = 0; k < 6; k++) { float v = lam[h * 6 + k]; l2[k] = v * v; }
    // basis order: (0,0),(1,0),(1,1),(2,0),(2,1),(2,2)
    float d0 = l2[0] + l2[1] + l2[3];   // W00
    float d1 = l2[1] + l2[2] + l2[4];   // W11
    float d2 = l2[3] + l2[4] + l2[5];   // W22
    float a  = -l2[1];                  // W01
    float c  = -l2[3];                  // W02
    float e  = -l2[4];                  // W12

    float b0 = fmaxf(b[h * 3 + 0], 0.0f);
    float b1 = fmaxf(b[h * 3 + 1], 0.0f);
    float b2 = fmaxf(b[h * 3 + 2], 0.0f);

    red[h * 8 + 0] = b0 + b1 + b2;
    red[h * 8 + 1] = d0;
    red[h * 8 + 2] = a;
    red[h * 8 + 3] = c;
    red[h * 8 + 4] = d1;
    red[h * 8 + 5] = e;
    red[h * 8 + 6] = d2;
    red[h * 8 + 7] = 0.0f;
    __syncthreads();

    for (int s = 128; s > 0; s >>= 1) {
        if (h < s) {
#pragma unroll
            for (int k = 0; k < 8; k++) red[h * 8 + k] += red[(h + s) * 8 + k];
        }
        __syncthreads();
    }

    if (h == 0) {
        g_wsum[0] = red[1];  // Wsum00
        g_wsum[1] = red[2];  // Wsum01
        g_wsum[2] = red[3];  // Wsum02
        g_wsum[3] = red[4];  // Wsum11
        g_wsum[4] = red[5];  // Wsum12
        g_wsum[5] = red[6];  // Wsum22
    }

    float inv = 0.15f / red[0];
    float bn0 = b0 * inv, bn1 = b1 * inv, bn2 = b2 * inv;

    float* t = g_table + h * TAB_STRIDE;
    t[0]  = d0;  t[1]  = d0;
    t[2]  = a;   t[3]  = a;
    t[4]  = c;   t[5]  = c;
    t[6]  = d1;  t[7]  = d1;
    t[8]  = e;   t[9]  = e;
    t[10] = d2;  t[11] = d2;
    t[12] = bn0; t[13] = bn1; t[14] = bn2; t[15] = 0.0f;
}

// ----------------------------------------------------------------------------
// Main kernel: 2 rows per thread (f32x2-packed), h-loop split across lane
// halves. Warp covers 16 row-pairs. 4096 warps = 1024 blocks x 128.
// ----------------------------------------------------------------------------
__global__ __launch_bounds__(128) void main_kernel(
    const float* __restrict__ state, float* __restrict__ out) {
    __shared__ float tab[HN * TAB_STRIDE];

    // cooperative table load (1024 float4)
    {
        const float4* g4 = (const float4*)g_table;
        float4* s4 = (float4*)tab;
#pragma unroll
        for (int i = 0; i < 8; i++) s4[threadIdx.x + i * 128] = g4[threadIdx.x + i * 128];
    }
    __syncthreads();

    int lane = threadIdx.x & 31;
    int wid  = threadIdx.x >> 5;
    int warpGlobal = blockIdx.x * 4 + wid;
    int g    = warpGlobal * 16 + (lane & 15);   // row-pair id: rows 2g, 2g+1
    int half = lane >> 4;                       // h range: [half*128, half*128+128)

    const float2* st = (const float2*)state + (size_t)g * 3;
    float2 v01  = st[0];
    float2 v2_0 = st[1];
    float2 v12  = st[2];

    float sa0 = deadband(v01.x),  sa1 = deadband(v01.y),  sa2 = deadband(v2_0.x);
    float sb0 = deadband(v2_0.y), sb1 = deadband(v12.x),  sb2 = deadband(v12.y);

    u64 S0 = pack2(sa0, sb0);
    u64 S1 = pack2(sa1, sb1);
    u64 S2 = pack2(sa2, sb2);

    u64 acc0 = 0ull, acc1 = 0ull, acc2 = 0ull;

    const float* tb = tab + half * (HN / 2) * TAB_STRIDE;

#pragma unroll 8
    for (int h = 0; h < HN / 2; h++) {
        const ulonglong2* tp = (const ulonglong2*)(tb + h * TAB_STRIDE);
        ulonglong2 p0 = tp[0];   // D0 | A    (each u64 = duplicated f32 pair)
        ulonglong2 p1 = tp[1];   // C  | D1
        ulonglong2 p2 = tp[2];   // E  | D2
        float4 q3 = ((const float4*)tp)[3];   // bn0 bn1 bn2 pad

        // sw = W s (symmetric), two rows packed
        u64 sw0 = ffma2(p1.x, S2, ffma2(p0.y, S1, fmul2(p0.x, S0)));
        u64 sw1 = ffma2(p2.x, S2, ffma2(p1.y, S1, fmul2(p0.y, S0)));
        u64 sw2 = ffma2(p2.y, S2, ffma2(p2.x, S1, fmul2(p1.x, S0)));

        float w0a, w0b, w1a, w1b, w2a, w2b;
        unpack2(sw0, w0a, w0b);
        unpack2(sw1, w1a, w1b);
        unpack2(sw2, w2a, w2b);

        // clamp(sw, -bn, bn): FMNMX with negate folded into source modifier
        float t0a = fminf(fmaxf(w0a, -q3.x), q3.x);
        float t0b = fminf(fmaxf(w0b, -q3.x), q3.x);
        float t1a = fminf(fmaxf(w1a, -q3.y), q3.y);
        float t1b = fminf(fmaxf(w1b, -q3.y), q3.y);
        float t2a = fminf(fmaxf(w2a, -q3.z), q3.z);
        float t2b = fminf(fmaxf(w2b, -q3.z), q3.z);

        acc0 = fadd2(acc0, pack2(t0a, t0b));
        acc1 = fadd2(acc1, pack2(t1a, t1b));
        acc2 = fadd2(acc2, pack2(t2a, t2b));
    }

    // combine the two h-halves (lane l <-> lane l^16 hold same row-pair)
    acc0 = fadd2(acc0, __shfl_xor_sync(0xFFFFFFFFu, acc0, 16));
    acc1 = fadd2(acc1, __shfl_xor_sync(0xFFFFFFFFu, acc1, 16));
    acc2 = fadd2(acc2, __shfl_xor_sync(0xFFFFFFFFu, acc2, 16));

    if (half == 0) {
        float a0, a0b, a1, a1b, a2, a2b;
        unpack2(acc0, a0, a0b);
        unpack2(acc1, a1, a1b);
        unpack2(acc2, a2, a2b);

        float ws00 = g_wsum[0], ws01 = g_wsum[1], ws02 = g_wsum[2];
        float ws11 = g_wsum[3], ws12 = g_wsum[4], ws22 = g_wsum[5];

        float la0 = ws00 * sa0 + ws01 * sa1 + ws02 * sa2;
        float la1 = ws01 * sa0 + ws11 * sa1 + ws12 * sa2;
        float la2 = ws02 * sa0 + ws12 * sa1 + ws22 * sa2;
        float lb0 = ws00 * sb0 + ws01 * sb1 + ws02 * sb2;
        float lb1 = ws01 * sb0 + ws11 * sb1 + ws12 * sb2;
        float lb2 = ws02 * sb0 + ws12 * sb1 + ws22 * sb2;

        float oA0 = la0 - a0  + 0.001f * sa0;
        float oA1 = la1 - a1  + 0.001f * sa1;
        float oA2 = la2 - a2  + 0.001f * sa2;
        float oB0 = lb0 - a0b + 0.001f * sb0;
        float oB1 = lb1 - a1b + 0.001f * sb1;
        float oB2 = lb2 - a2b + 0.001f * sb2;

        float2* op = (float2*)out + (size_t)g * 3;
        op[0] = make_float2(oA0, oA1);
        op[1] = make_float2(oA2, oB0);
        op[2] = make_float2(oB1, oB2);
    }
}

extern "C" void kernel_launch(void* const* d_in, const int* in_sizes, int n_in,
                              void* d_out, int out_size) {
    const float* state = (const float*)d_in[0];   // [131072, 3]
    const float* b     = (const float*)d_in[1];   // [256, 3]
    const float* lam   = (const float*)d_in[2];   // [256, 6]
    float* out = (float*)d_out;                   // [131072, 3]

    prep_kernel<<<1, HN>>>(b, lam);
    // 65536 row-pairs, 16 pairs per warp (x2 h-halves), 4 warps per block
    main_kernel<<<1024, 128>>>(state, out);
}